// round 16
// baseline (speedup 1.0000x reference)
#include <cuda_runtime.h>
#include <cuda_bf16.h>
#include <cstdint>

// ---------------- problem constants ----------------
#define NQ_   900
#define NQP_  960
#define B_    8
#define D_    256
#define H_    8
#define DH_   32
#define L_    4
#define P_    5
#define S_    21760
#define DFF_  1024
#define NTOK_ (NQ_ * B_)      // 7200
#define MTOK_ (S_ * B_)       // 174080
#define KOFF_ (B_*H_*NQP_*DH_)   // offset of kl within g_khl

__device__ __constant__ int c_Hl[4]    = {128, 64, 32, 16};
__device__ __constant__ int c_start[4] = {0, 16384, 20480, 21504};

// ---------------- scratch ----------------
__device__ float g_q[B_*H_*NQ_*DH_];
__device__ float g_v[B_*H_*NQ_*DH_];
__device__ __align__(16) __nv_bfloat16 g_khl[2*KOFF_];
__device__ __align__(16) __nv_bfloat16 g_vh[B_*H_*DH_*NQP_];
__device__ __align__(16) __nv_bfloat16 g_vl[B_*H_*DH_*NQP_];
__device__ __align__(16) __nv_bfloat16 g_valbf[B_*H_*S_*DH_];
__device__ float g_attn[NTOK_*D_];
__device__ float g_saproj[NTOK_*D_];
__device__ float g_tgt1[NTOK_*D_];
__device__ float g_off[NTOK_*(H_*L_*P_*2)];
__device__ float g_aw[NTOK_*(H_*L_*P_)];
__device__ float g_ca[NTOK_*D_];
__device__ float g_caproj[NTOK_*D_];
__device__ float g_tgt2[NTOK_*D_];
__device__ float g_ffh[NTOK_*DFF_];
__device__ float g_ff[NTOK_*D_];

// ---------------- small helpers ----------------
__device__ __forceinline__ uint32_t su32(const void* p) {
    uint32_t a;
    asm("{ .reg .u64 t; cvta.to.shared.u64 t, %1; cvt.u32.u64 %0, t; }" : "=r"(a) : "l"(p));
    return a;
}
__device__ __forceinline__ uint32_t pk(float a, float b) {
    __nv_bfloat162 h = __floats2bfloat162_rn(a, b);
    return reinterpret_cast<uint32_t&>(h);
}
__device__ __forceinline__ void ldsm4(uint32_t addr, uint32_t* r) {
    asm volatile("ldmatrix.sync.aligned.m8n8.x4.shared.b16 {%0,%1,%2,%3}, [%4];"
                 : "=r"(r[0]), "=r"(r[1]), "=r"(r[2]), "=r"(r[3]) : "r"(addr));
}
#define MMA16816(c, a, b0r, b1r) \
    asm volatile("mma.sync.aligned.m16n8k16.row.col.f32.bf16.bf16.f32 " \
                 "{%0,%1,%2,%3},{%4,%5,%6,%7},{%8,%9},{%0,%1,%2,%3};" \
                 : "+f"((c)[0]), "+f"((c)[1]), "+f"((c)[2]), "+f"((c)[3]) \
                 : "r"((a)[0]), "r"((a)[1]), "r"((a)[2]), "r"((a)[3]), \
                   "r"(b0r), "r"(b1r))

// ================= mma.sync bf16 fp32-emulated GEMM =================
// TERMS==3: D = Ahi*Bhi + Ahi*Blo + Alo*Bhi ; TERMS==2: drops Alo*Bhi.
// SMEM layout is TERMS-dependent: 2-term skips A-lo buffers entirely
// (40960 B -> 5 CTAs/SM vs 61440 B -> 3 CTAs/SM).
#define A_PITCH 80
#define A_TILE  10240
#define B_TILE  5120
#define SMT3 (4*A_TILE + 4*B_TILE)   // 61440
#define SMT2 (2*A_TILE + 4*B_TILE)   // 40960

// OMODE 0: C[r*N+n] fp32
// OMODE 1: heads layout fp32; head hh=n>>5: hh<8 -> C, hh>=8 -> C2 (h'=hh-8)
// OMODE 2: heads layout bf16 into (bf16*)C (N<=256)
// OMODE 3: QK fused: hh<8 -> C fp32 heads (nrows); hh>=8 -> bf16 hi/lo into
//          (bf16*)C2 (+KOFF_ for lo), padded heads layout nrows=NQP_
template<int AMODE, int OMODE, bool RELU, int TERMS>
__global__ void __launch_bounds__(256) tgemm(
    const float* __restrict__ A0, const float* __restrict__ A1,
    const float* __restrict__ W,  const float* __restrict__ bias,
    float* __restrict__ C, float* __restrict__ C2,
    int M, int N, int K, int nrows)
{
    extern __shared__ char sm[];
    constexpr int ATILES = (TERMS == 3) ? 2 : 1;            // hi (+lo)
    constexpr int BBASE  = 2 * ATILES * A_TILE;             // B region start

    const int tid  = threadIdx.x;
    const int lane = tid & 31;
    const int wid  = tid >> 5;
    const int wm   = wid & 3;
    const int wn   = wid >> 2;
    const int colBase = blockIdx.x * 64;
    const int rowBase = blockIdx.y * 128;

    const uint32_t smBase = su32(sm);
    auto AOFFc = [&](int bf, int s) { return (bf * ATILES + s) * A_TILE; };
    auto BOFFc = [&](int bf, int s) { return BBASE + (bf * 2 + s) * B_TILE; };

    float4 pa[4];
    float4 pb[2];

    auto ldg_chunk = [&](int k0) {
#pragma unroll
        for (int i = 0; i < 4; i++) {
            int idx = tid + i * 256;
            int row = idx >> 3, f4 = idx & 7;
            int gr = rowBase + row;
            float4 v = make_float4(0.f, 0.f, 0.f, 0.f);
            if (gr < M) {
                v = *(const float4*)(A0 + (size_t)gr * K + k0 + f4 * 4);
                if (AMODE) {
                    float4 u = *(const float4*)(A1 + (size_t)gr * K + k0 + f4 * 4);
                    v.x += u.x; v.y += u.y; v.z += u.z; v.w += u.w;
                }
            }
            pa[i] = v;
        }
#pragma unroll
        for (int i = 0; i < 2; i++) {
            int idx = tid + i * 256;
            int row = idx >> 3, f4 = idx & 7;
            int gn = colBase + row;
            pb[i] = (gn < N) ? *(const float4*)(W + (size_t)gn * K + k0 + f4 * 4)
                             : make_float4(0.f, 0.f, 0.f, 0.f);
        }
    };

    auto sts_chunk = [&](int bf) {
#pragma unroll
        for (int i = 0; i < 4; i++) {
            int idx = tid + i * 256;
            int row = idx >> 3, f4 = idx & 7;
            float4 v = pa[i];
            float hx = __bfloat162float(__float2bfloat16_rn(v.x));
            float hy = __bfloat162float(__float2bfloat16_rn(v.y));
            float hz = __bfloat162float(__float2bfloat16_rn(v.z));
            float hw = __bfloat162float(__float2bfloat16_rn(v.w));
            uint2 Hi = make_uint2(pk(hx, hy), pk(hz, hw));
            *(uint2*)(sm + AOFFc(bf, 0) + row * A_PITCH + f4 * 8) = Hi;
            if (TERMS == 3) {
                uint2 Lo = make_uint2(pk(v.x - hx, v.y - hy), pk(v.z - hz, v.w - hw));
                *(uint2*)(sm + AOFFc(bf, 1) + row * A_PITCH + f4 * 8) = Lo;
            }
        }
#pragma unroll
        for (int i = 0; i < 2; i++) {
            int idx = tid + i * 256;
            int row = idx >> 3, f4 = idx & 7;
            float4 v = pb[i];
            float hx = __bfloat162float(__float2bfloat16_rn(v.x));
            float hy = __bfloat162float(__float2bfloat16_rn(v.y));
            float hz = __bfloat162float(__float2bfloat16_rn(v.z));
            float hw = __bfloat162float(__float2bfloat16_rn(v.w));
            uint2 Hi = make_uint2(pk(hx, hy), pk(hz, hw));
            uint2 Lo = make_uint2(pk(v.x - hx, v.y - hy), pk(v.z - hz, v.w - hw));
            *(uint2*)(sm + BOFFc(bf, 0) + row * A_PITCH + f4 * 8) = Hi;
            *(uint2*)(sm + BOFFc(bf, 1) + row * A_PITCH + f4 * 8) = Lo;
        }
    };

    float acc[2][4][4];
#pragma unroll
    for (int tm = 0; tm < 2; tm++)
#pragma unroll
        for (int tn = 0; tn < 4; tn++)
#pragma unroll
            for (int j = 0; j < 4; j++) acc[tm][tn][j] = 0.f;

    const int laneRow  = lane & 15;
    const int laneHalf = (lane & 16) ? 16 : 0;
    const uint32_t aRowOff  = (uint32_t)(wm * 32 + laneRow) * A_PITCH + laneHalf;
    const uint32_t bRowOff0 = (uint32_t)(wn * 32 + laneRow) * A_PITCH + laneHalf;
    const uint32_t bRowOff1 = (uint32_t)(wn * 32 + 16 + laneRow) * A_PITCH + laneHalf;

    const int NC = K >> 5;
    ldg_chunk(0);

    for (int c = 0; c < NC; c++) {
        int bf = c & 1;
        sts_chunk(bf);
        __syncthreads();
        if (c + 1 < NC) ldg_chunk((c + 1) * 32);

        const uint32_t aHiB = smBase + AOFFc(bf, 0) + aRowOff;
        const uint32_t aLoB = smBase + AOFFc(bf, TERMS == 3 ? 1 : 0) + aRowOff;
        const uint32_t bHiB0 = smBase + BOFFc(bf, 0) + bRowOff0;
        const uint32_t bHiB1 = smBase + BOFFc(bf, 0) + bRowOff1;
        const uint32_t bLoB0 = smBase + BOFFc(bf, 1) + bRowOff0;
        const uint32_t bLoB1 = smBase + BOFFc(bf, 1) + bRowOff1;

#pragma unroll
        for (int ks = 0; ks < 2; ks++) {
            uint32_t kof = ks * 32;
            uint32_t aH[2][4], aL[2][4], bH0[4], bH1[4], bL0[4], bL1[4];
            ldsm4(aHiB + kof,                aH[0]);
            ldsm4(aHiB + 16 * A_PITCH + kof, aH[1]);
            if (TERMS == 3) {
                ldsm4(aLoB + kof,                aL[0]);
                ldsm4(aLoB + 16 * A_PITCH + kof, aL[1]);
            }
            ldsm4(bHiB0 + kof, bH0);
            ldsm4(bHiB1 + kof, bH1);
            ldsm4(bLoB0 + kof, bL0);
            ldsm4(bLoB1 + kof, bL1);

            uint32_t b0h[4] = {bH0[0], bH0[1], bH1[0], bH1[1]};
            uint32_t b1h[4] = {bH0[2], bH0[3], bH1[2], bH1[3]};
            uint32_t b0l[4] = {bL0[0], bL0[1], bL1[0], bL1[1]};
            uint32_t b1l[4] = {bL0[2], bL0[3], bL1[2], bL1[3]};

#pragma unroll
            for (int tm = 0; tm < 2; tm++) {
#pragma unroll
                for (int tn = 0; tn < 4; tn++) {
                    MMA16816(acc[tm][tn], aH[tm], b0h[tn], b1h[tn]);
                    MMA16816(acc[tm][tn], aH[tm], b0l[tn], b1l[tn]);
                    if (TERMS == 3)
                        MMA16816(acc[tm][tn], aL[tm], b0h[tn], b1h[tn]);
                }
            }
        }
        // no trailing sync: double buffering makes the pre-MMA sync sufficient
    }

    const int g  = lane >> 2;
    const int t4 = lane & 3;
#pragma unroll
    for (int tm = 0; tm < 2; tm++) {
        int row0 = rowBase + wm * 32 + tm * 16 + g;
#pragma unroll
        for (int tn = 0; tn < 4; tn++) {
            int col = colBase + wn * 32 + tn * 8 + t4 * 2;
            if (col >= N) continue;
            float b0 = bias[col], b1 = bias[col + 1];
            float* cc = acc[tm][tn];
            float v00 = cc[0] + b0, v01 = cc[1] + b1;
            float v10 = cc[2] + b0, v11 = cc[3] + b1;
            if (RELU) {
                v00 = fmaxf(v00, 0.f); v01 = fmaxf(v01, 0.f);
                v10 = fmaxf(v10, 0.f); v11 = fmaxf(v11, 0.f);
            }
            if (OMODE == 0) {
                if (row0 < M)     *(float2*)(C + (size_t)row0 * N + col)       = make_float2(v00, v01);
                if (row0 + 8 < M) *(float2*)(C + (size_t)(row0 + 8) * N + col) = make_float2(v10, v11);
            } else if (OMODE == 1) {
                int hh = col >> 5, wi = col & 31;
                float* dst = (hh < 8) ? C : C2;
                int hp = hh & 7;
                if (row0 < M) {
                    int s = row0 >> 3, bb = row0 & 7;
                    *(float2*)(dst + (((size_t)(bb * 8 + hp)) * nrows + s) * 32 + wi) = make_float2(v00, v01);
                }
                if (row0 + 8 < M) {
                    int r1 = row0 + 8;
                    int s = r1 >> 3, bb = r1 & 7;
                    *(float2*)(dst + (((size_t)(bb * 8 + hp)) * nrows + s) * 32 + wi) = make_float2(v10, v11);
                }
            } else if (OMODE == 2) {
                int hh = col >> 5, wi = col & 31;
                __nv_bfloat16* dst = (__nv_bfloat16*)C;
                if (row0 < M) {
                    int s = row0 >> 3, bb = row0 & 7;
                    *(uint32_t*)(dst + (((size_t)(bb * 8 + hh)) * nrows + s) * 32 + wi) = pk(v00, v01);
                }
                if (row0 + 8 < M) {
                    int r1 = row0 + 8;
                    int s = r1 >> 3, bb = r1 & 7;
                    *(uint32_t*)(dst + (((size_t)(bb * 8 + hh)) * nrows + s) * 32 + wi) = pk(v10, v11);
                }
            } else {   // OMODE 3
                int hh = col >> 5, wi = col & 31;
                if (hh < 8) {
                    if (row0 < M) {
                        int s = row0 >> 3, bb = row0 & 7;
                        *(float2*)(C + (((size_t)(bb * 8 + hh)) * nrows + s) * 32 + wi) = make_float2(v00, v01);
                    }
                    if (row0 + 8 < M) {
                        int r1 = row0 + 8;
                        int s = r1 >> 3, bb = r1 & 7;
                        *(float2*)(C + (((size_t)(bb * 8 + hh)) * nrows + s) * 32 + wi) = make_float2(v10, v11);
                    }
                } else {
                    int hp = hh - 8;
                    __nv_bfloat16* kh = (__nv_bfloat16*)C2;
                    if (row0 < M) {
                        int s = row0 >> 3, bb = row0 & 7;
                        size_t o = (((size_t)(bb * 8 + hp)) * NQP_ + s) * 32 + wi;
                        float h0 = __bfloat162float(__float2bfloat16_rn(v00));
                        float h1 = __bfloat162float(__float2bfloat16_rn(v01));
                        *(uint32_t*)(kh + o)         = pk(h0, h1);
                        *(uint32_t*)(kh + KOFF_ + o) = pk(v00 - h0, v01 - h1);
                    }
                    if (row0 + 8 < M) {
                        int r1 = row0 + 8;
                        int s = r1 >> 3, bb = r1 & 7;
                        size_t o = (((size_t)(bb * 8 + hp)) * NQP_ + s) * 32 + wi;
                        float h0 = __bfloat162float(__float2bfloat16_rn(v10));
                        float h1 = __bfloat162float(__float2bfloat16_rn(v11));
                        *(uint32_t*)(kh + o)         = pk(h0, h1);
                        *(uint32_t*)(kh + KOFF_ + o) = pk(v10 - h0, v11 - h1);
                    }
                }
            }
        }
    }
}

// ---------------- prep: V fp32 -> transposed bf16 hi/lo via smem tiles --------
__global__ void prep_v(const float* __restrict__ v,
                       __nv_bfloat16* __restrict__ vh, __nv_bfloat16* __restrict__ vl)
{
    __shared__ float t[32][33];
    const int bh = blockIdx.y;
    const int kt = blockIdx.x * 32;
    const int ch = threadIdx.x & 31;
    const int r  = threadIdx.x >> 5;

#pragma unroll
    for (int i = 0; i < 4; i++) {
        int key = kt + r + i * 8;
        t[r + i * 8][ch] = (key < NQ_) ? v[((size_t)bh * NQ_ + key) * 32 + ch] : 0.f;
    }
    __syncthreads();
#pragma unroll
    for (int i = 0; i < 4; i++) {
        int ch2 = r + i * 8;
        float val = t[ch][ch2];
        __nv_bfloat16 h = __float2bfloat16_rn(val);
        size_t o = ((size_t)bh * 32 + ch2) * NQP_ + kt + ch;
        vh[o] = h;
        vl[o] = __float2bfloat16_rn(val - __bfloat162float(h));
    }
}

// ---------------- mma.sync flash self-attention -------------------------------
#define KS_PITCH 80
#define VS_PITCH 144
__global__ void __launch_bounds__(128) attn_mma(
    const float* __restrict__ q,
    const __nv_bfloat16* __restrict__ kh, const __nv_bfloat16* __restrict__ kl,
    const __nv_bfloat16* __restrict__ vh, const __nv_bfloat16* __restrict__ vl,
    float* __restrict__ out)
{
    __shared__ __align__(16) char KsH[64 * KS_PITCH];
    __shared__ __align__(16) char KsL[64 * KS_PITCH];
    __shared__ __align__(16) char VsH[32 * VS_PITCH];
    __shared__ __align__(16) char VsL[32 * VS_PITCH];

    const int bh   = blockIdx.y;
    const int q0   = blockIdx.x * 64;
    const int tid  = threadIdx.x;
    const int lane = tid & 31;
    const int w    = tid >> 5;
    const int g    = lane >> 2;
    const int t4   = lane & 3;
    const int laneRow  = lane & 15;
    const int laneHalf = (lane & 16) ? 16 : 0;

    const uint32_t sKH = su32(KsH), sKL = su32(KsL);
    const uint32_t sVH = su32(VsH), sVL = su32(VsL);
    const float scale = 0.17677669529663687f;

#pragma unroll
    for (int i = 0; i < 8; i++) {
        int p = tid + i * 128;
        int row = p >> 4, chp = p & 15;
        int gq = q0 + row;
        float a0 = 0.f, a1 = 0.f;
        if (gq < NQ_) {
            const float* src = q + ((size_t)bh * NQ_ + gq) * 32 + chp * 2;
            a0 = src[0] * scale; a1 = src[1] * scale;
        }
        float h0 = __bfloat162float(__float2bfloat16_rn(a0));
        float h1 = __bfloat162float(__float2bfloat16_rn(a1));
        *(uint32_t*)(KsH + row * KS_PITCH + chp * 4) = pk(h0, h1);
        *(uint32_t*)(KsL + row * KS_PITCH + chp * 4) = pk(a0 - h0, a1 - h1);
    }
    __syncthreads();

    uint32_t aQh[2][4], aQl[2][4];
#pragma unroll
    for (int kc = 0; kc < 2; kc++) {
        ldsm4(sKH + (w * 16 + laneRow) * KS_PITCH + laneHalf + kc * 32, aQh[kc]);
        ldsm4(sKL + (w * 16 + laneRow) * KS_PITCH + laneHalf + kc * 32, aQl[kc]);
    }
    __syncthreads();

    float sO[4][4];
#pragma unroll
    for (int tn = 0; tn < 4; tn++)
#pragma unroll
        for (int j = 0; j < 4; j++) sO[tn][j] = 0.f;
    float m0 = -1e30f, m1 = -1e30f, l0 = 0.f, l1 = 0.f;

    for (int kt = 0; kt < NQP_; kt += 64) {
#pragma unroll
        for (int i = 0; i < 2; i++) {
            int idx = tid + i * 128;
            int row = idx >> 2, seg = idx & 3;
            const uint4* srcH = (const uint4*)(kh + ((size_t)bh * NQP_ + kt + row) * 32 + seg * 8);
            const uint4* srcL = (const uint4*)(kl + ((size_t)bh * NQP_ + kt + row) * 32 + seg * 8);
            *(uint4*)(KsH + row * KS_PITCH + seg * 16) = *srcH;
            *(uint4*)(KsL + row * KS_PITCH + seg * 16) = *srcL;
            int vrow = idx >> 3, vseg = idx & 7;
            const uint4* vsrcH = (const uint4*)(vh + ((size_t)bh * 32 + vrow) * NQP_ + kt + vseg * 8);
            const uint4* vsrcL = (const uint4*)(vl + ((size_t)bh * 32 + vrow) * NQP_ + kt + vseg * 8);
            *(uint4*)(VsH + vrow * VS_PITCH + vseg * 16) = *vsrcH;
            *(uint4*)(VsL + vrow * VS_PITCH + vseg * 16) = *vsrcL;
        }
        __syncthreads();

        float sS[8][4];
#pragma unroll
        for (int tn = 0; tn < 8; tn++)
#pragma unroll
            for (int j = 0; j < 4; j++) sS[tn][j] = 0.f;

#pragma unroll
        for (int kc = 0; kc < 2; kc++) {
#pragma unroll
            for (int kg = 0; kg < 4; kg++) {
                uint32_t bKh[4], bKl[4];
                ldsm4(sKH + (kg * 16 + laneRow) * KS_PITCH + laneHalf + kc * 32, bKh);
                ldsm4(sKL + (kg * 16 + laneRow) * KS_PITCH + laneHalf + kc * 32, bKl);
                float* c0 = sS[kg * 2];
                float* c1 = sS[kg * 2 + 1];
                MMA16816(c0, aQh[kc], bKh[0], bKh[2]);
                MMA16816(c0, aQh[kc], bKl[0], bKl[2]);
                MMA16816(c0, aQl[kc], bKh[0], bKh[2]);
                MMA16816(c1, aQh[kc], bKh[1], bKh[3]);
                MMA16816(c1, aQh[kc], bKl[1], bKl[3]);
                MMA16816(c1, aQl[kc], bKh[1], bKh[3]);
            }
        }

        if (kt + 64 > NQ_) {
#pragma unroll
            for (int tn = 0; tn < 8; tn++) {
                int k0 = kt + tn * 8 + t4 * 2;
                if (k0 >= NQ_)     { sS[tn][0] = -1e30f; sS[tn][2] = -1e30f; }
                if (k0 + 1 >= NQ_) { sS[tn][1] = -1e30f; sS[tn][3] = -1e30f; }
            }
        }

        float mx0 = -1e30f, mx1 = -1e30f;
#pragma unroll
        for (int tn = 0; tn < 8; tn++) {
            mx0 = fmaxf(mx0, fmaxf(sS[tn][0], sS[tn][1]));
            mx1 = fmaxf(mx1, fmaxf(sS[tn][2], sS[tn][3]));
        }
        mx0 = fmaxf(mx0, __shfl_xor_sync(0xffffffffu, mx0, 1));
        mx0 = fmaxf(mx0, __shfl_xor_sync(0xffffffffu, mx0, 2));
        mx1 = fmaxf(mx1, __shfl_xor_sync(0xffffffffu, mx1, 1));
        mx1 = fmaxf(mx1, __shfl_xor_sync(0xffffffffu, mx1, 2));
        float nm0 = fmaxf(m0, mx0), nm1 = fmaxf(m1, mx1);
        float cr0 = __expf(m0 - nm0), cr1 = __expf(m1 - nm1);
        m0 = nm0; m1 = nm1;
        float rs0 = 0.f, rs1 = 0.f;
#pragma unroll
        for (int tn = 0; tn < 8; tn++) {
            sS[tn][0] = __expf(sS[tn][0] - nm0);
            sS[tn][1] = __expf(sS[tn][1] - nm0);
            sS[tn][2] = __expf(sS[tn][2] - nm1);
            sS[tn][3] = __expf(sS[tn][3] - nm1);
            rs0 += sS[tn][0] + sS[tn][1];
            rs1 += sS[tn][2] + sS[tn][3];
        }
        rs0 += __shfl_xor_sync(0xffffffffu, rs0, 1);
        rs0 += __shfl_xor_sync(0xffffffffu, rs0, 2);
        rs1 += __shfl_xor_sync(0xffffffffu, rs1, 1);
        rs1 += __shfl_xor_sync(0xffffffffu, rs1, 2);
        l0 = l0 * cr0 + rs0;
        l1 = l1 * cr1 + rs1;
#pragma unroll
        for (int tn = 0; tn < 4; tn++) {
            sO[tn][0] *= cr0; sO[tn][1] *= cr0;
            sO[tn][2] *= cr1; sO[tn][3] *= cr1;
        }

#pragma unroll
        for (int kc = 0; kc < 4; kc++) {
            const float* cA = sS[kc * 2];
            const float* cB = sS[kc * 2 + 1];
            float hA0 = __bfloat162float(__float2bfloat16_rn(cA[0]));
            float hA1 = __bfloat162float(__float2bfloat16_rn(cA[1]));
            float hA2 = __bfloat162float(__float2bfloat16_rn(cA[2]));
            float hA3 = __bfloat162float(__float2bfloat16_rn(cA[3]));
            float hB0 = __bfloat162float(__float2bfloat16_rn(cB[0]));
            float hB1 = __bfloat162float(__float2bfloat16_rn(cB[1]));
            float hB2 = __bfloat162float(__float2bfloat16_rn(cB[2]));
            float hB3 = __bfloat162float(__float2bfloat16_rn(cB[3]));
            uint32_t pH[4] = { pk(hA0, hA1), pk(hA2, hA3), pk(hB0, hB1), pk(hB2, hB3) };
            uint32_t pL[4] = { pk(cA[0]-hA0, cA[1]-hA1), pk(cA[2]-hA2, cA[3]-hA3),
                               pk(cB[0]-hB0, cB[1]-hB1), pk(cB[2]-hB2, cB[3]-hB3) };
#pragma unroll
            for (int ng = 0; ng < 2; ng++) {
                uint32_t bVh[4], bVl[4];
                ldsm4(sVH + (ng * 16 + laneRow) * VS_PITCH + laneHalf + kc * 32, bVh);
                ldsm4(sVL + (ng * 16 + laneRow) * VS_PITCH + laneHalf + kc * 32, bVl);
                float* o0 = sO[ng * 2];
                float* o1 = sO[ng * 2 + 1];
                MMA16816(o0, pH, bVh[0], bVh[2]);
                MMA16816(o0, pH, bVl[0], bVl[2]);
                MMA16816(o0, pL, bVh[0], bVh[2]);
                MMA16816(o1, pH, bVh[1], bVh[3]);
                MMA16816(o1, pH, bVl[1], bVl[3]);
                MMA16816(o1, pL, bVh[1], bVh[3]);
            }
        }
        __syncthreads();
    }

    const int b = bh >> 3, h = bh & 7;
    float inv0 = 1.f / l0, inv1 = 1.f / l1;
    int r0 = q0 + w * 16 + g;
    int r1 = r0 + 8;
#pragma unroll
    for (int tn = 0; tn < 4; tn++) {
        int col = h * 32 + tn * 8 + t4 * 2;
        if (r0 < NQ_)
            *(float2*)(out + ((size_t)r0 * B_ + b) * D_ + col) =
                make_float2(sO[tn][0] * inv0, sO[tn][1] * inv0);
        if (r1 < NQ_)
            *(float2*)(out + ((size_t)r1 * B_ + b) * D_ + col) =
                make_float2(sO[tn][2] * inv1, sO[tn][3] * inv1);
    }
}

// ---------------- layer norm: warp per token, single-pass sum+sumsq ----------
__global__ void __launch_bounds__(256) ln_kernel(
    const float* __restrict__ a, const float* __restrict__ r,
    const float* __restrict__ g, const float* __restrict__ be,
    float* __restrict__ out)
{
    const int lane = threadIdx.x & 31;
    const int t = blockIdx.x * 8 + (threadIdx.x >> 5);

    const float* pa = a + (size_t)t * D_;
    const float* pr = r + (size_t)t * D_;

    float x[8];
    float s = 0.f, s2 = 0.f;
#pragma unroll
    for (int j = 0; j < 8; j++) {
        int i = lane + j * 32;
        float v = pa[i] + pr[i];
        x[j] = v;
        s += v;
        s2 = fmaf(v, v, s2);
    }
#pragma unroll
    for (int o = 16; o; o >>= 1) {
        s  += __shfl_xor_sync(0xffffffffu, s,  o);
        s2 += __shfl_xor_sync(0xffffffffu, s2, o);
    }
    float mean = s * (1.f / 256.f);
    float var  = fmaf(s2, 1.f / 256.f, -mean * mean);
    float rstd = rsqrtf(var + 1e-5f);

    float* po = out + (size_t)t * D_;
#pragma unroll
    for (int j = 0; j < 8; j++) {
        int i = lane + j * 32;
        po[i] = (x[j] - mean) * rstd * g[i] + be[i];
    }
}

// ---------------- deformable sampling (bf16 value) ----------------
__global__ void sample_kernel(const float* __restrict__ off, const float* __restrict__ awl,
                              const float* __restrict__ refp,
                              const __nv_bfloat16* __restrict__ val,
                              float* __restrict__ out)
{
    const int gw   = blockIdx.x * 8 + (threadIdx.x >> 5);
    const int lane = threadIdx.x & 31;
    const int t = gw >> 3;
    const int h = gw & 7;
    const int b = t & 7;

    float logit = (lane < 20) ? awl[(size_t)t * 160 + h * 20 + lane] : -1e30f;
    float mx = logit;
#pragma unroll
    for (int o = 16; o; o >>= 1) mx = fmaxf(mx, __shfl_xor_sync(0xffffffffu, mx, o));
    float e = (lane < 20) ? __expf(logit - mx) : 0.f;
    float sm = e;
#pragma unroll
    for (int o = 16; o; o >>= 1) sm += __shfl_xor_sync(0xffffffffu, sm, o);
    float pw = e / sm;

    const float* rp = refp + (size_t)t * 16;
    const float* op = off + (size_t)t * 320 + h * 40;

    float acc = 0.f;
#pragma unroll
    for (int l = 0; l < 4; l++) {
        const int Wl = c_Hl[l];
        const int Hl = c_Hl[l];
        const float r0 = rp[l * 4 + 0], r1 = rp[l * 4 + 1];
        const float r2 = rp[l * 4 + 2], r3 = rp[l * 4 + 3];
        const __nv_bfloat16* vbase = val + ((size_t)(b * 8 + h) * S_ + c_start[l]) * 32;
#pragma unroll
        for (int p = 0; p < 5; p++) {
            float aw = __shfl_sync(0xffffffffu, pw, l * 5 + p);
            float ox = op[(l * 5 + p) * 2 + 0];
            float oy = op[(l * 5 + p) * 2 + 1];
            float x = (r0 + ox * 0.2f * r2 * 0.5f) * (float)Wl - 0.5f;
            float y = (r1 + oy * 0.2f * r3 * 0.5f) * (float)Hl - 0.5f;
            float x0f = floorf(x), y0f = floorf(y);
            float fx = x - x0f, fy = y - y0f;
            int x0 = (int)x0f, y0 = (int)y0f;
#pragma unroll
            for (int dy = 0; dy < 2; dy++) {
#pragma unroll
                for (int dx = 0; dx < 2; dx++) {
                    int xi = x0 + dx, yi = y0 + dy;
                    float w = (dx ? fx : 1.f - fx) * (dy ? fy : 1.f - fy);
                    bool valid = (xi >= 0) && (xi < Wl) && (yi >= 0) && (yi < Hl);
                    if (valid && w != 0.f)
                        acc = fmaf(aw * w,
                                   __bfloat162float(vbase[((size_t)yi * Wl + xi) * 32 + lane]),
                                   acc);
                }
            }
        }
    }
    out[(size_t)t * D_ + h * 32 + lane] = acc;
}

// ---------------- host launcher ----------------
static inline int cdiv(int a, int b) { return (a + b - 1) / b; }

extern "C" void kernel_launch(void* const* d_in, const int* in_sizes, int n_in,
                              void* d_out, int out_size)
{
    const float* tgt     = (const float*)d_in[0];
    const float* pos     = (const float*)d_in[1];
    const float* refp    = (const float*)d_in[2];
    const float* memory  = (const float*)d_in[3];
    const float* sa_in_w = (const float*)d_in[4];
    const float* sa_in_b = (const float*)d_in[5];
    const float* sa_out_w= (const float*)d_in[6];
    const float* sa_out_b= (const float*)d_in[7];
    const float* off_w   = (const float*)d_in[8];
    const float* off_b   = (const float*)d_in[9];
    const float* aw_w    = (const float*)d_in[10];
    const float* aw_b    = (const float*)d_in[11];
    const float* val_w   = (const float*)d_in[12];
    const float* val_b   = (const float*)d_in[13];
    const float* co_w    = (const float*)d_in[14];
    const float* co_b    = (const float*)d_in[15];
    const float* w1      = (const float*)d_in[16];
    const float* b1      = (const float*)d_in[17];
    const float* w2      = (const float*)d_in[18];
    const float* b2      = (const float*)d_in[19];
    const float* ln1_g   = (const float*)d_in[20];
    const float* ln1_b   = (const float*)d_in[21];
    const float* ln2_g   = (const float*)d_in[22];
    const float* ln2_b   = (const float*)d_in[23];
    const float* ln3_g   = (const float*)d_in[24];
    const float* ln3_b   = (const float*)d_in[25];
    float* out = (float*)d_out;

    void *p;
    cudaGetSymbolAddress(&p, g_q);      float* q_     = (float*)p;
    cudaGetSymbolAddress(&p, g_v);      float* v_     = (float*)p;
    cudaGetSymbolAddress(&p, g_khl);    __nv_bfloat16* kh_ = (__nv_bfloat16*)p;
    __nv_bfloat16* kl_ = kh_ + KOFF_;
    cudaGetSymbolAddress(&p, g_vh);     __nv_bfloat16* vh_ = (__nv_bfloat16*)p;
    cudaGetSymbolAddress(&p, g_vl);     __nv_bfloat16* vl_ = (__nv_bfloat16*)p;
    cudaGetSymbolAddress(&p, g_valbf);  __nv_bfloat16* valbf_ = (__nv_bfloat16*)p;
    cudaGetSymbolAddress(&p, g_attn);   float* attn_  = (float*)p;
    cudaGetSymbolAddress(&p, g_saproj); float* sap_   = (float*)p;
    cudaGetSymbolAddress(&p, g_tgt1);   float* tgt1_  = (float*)p;
    cudaGetSymbolAddress(&p, g_off);    float* off_   = (float*)p;
    cudaGetSymbolAddress(&p, g_aw);     float* aw_    = (float*)p;
    cudaGetSymbolAddress(&p, g_ca);     float* ca_    = (float*)p;
    cudaGetSymbolAddress(&p, g_caproj); float* cap_   = (float*)p;
    cudaGetSymbolAddress(&p, g_tgt2);   float* tgt2_  = (float*)p;
    cudaGetSymbolAddress(&p, g_ffh);    float* ffh_   = (float*)p;
    cudaGetSymbolAddress(&p, g_ff);     float* ff_    = (float*)p;

    // one-time setup (first call is the uncaptured correctness run)
    static cudaStream_t s1 = nullptr, s2 = nullptr;
    static cudaEvent_t evFork = nullptr, evFork2 = nullptr, evJoin1 = nullptr, evJoin2 = nullptr;
    static bool attr_done = false;
    if (!attr_done) {
        cudaFuncSetAttribute(tgemm<1,3,false,3>, cudaFuncAttributeMaxDynamicSharedMemorySize, SMT3);
        cudaFuncSetAttribute(tgemm<0,1,false,3>, cudaFuncAttributeMaxDynamicSharedMemorySize, SMT3);
        cudaFuncSetAttribute(tgemm<0,0,false,3>, cudaFuncAttributeMaxDynamicSharedMemorySize, SMT3);
        cudaFuncSetAttribute(tgemm<0,2,false,2>, cudaFuncAttributeMaxDynamicSharedMemorySize, SMT2);
        cudaFuncSetAttribute(tgemm<1,0,false,3>, cudaFuncAttributeMaxDynamicSharedMemorySize, SMT3);
        cudaFuncSetAttribute(tgemm<0,0,true ,2>, cudaFuncAttributeMaxDynamicSharedMemorySize, SMT2);
        cudaFuncSetAttribute(tgemm<0,0,false,2>, cudaFuncAttributeMaxDynamicSharedMemorySize, SMT2);
        cudaStreamCreateWithFlags(&s1, cudaStreamNonBlocking);
        cudaStreamCreateWithFlags(&s2, cudaStreamNonBlocking);
        cudaEventCreateWithFlags(&evFork,  cudaEventDisableTiming);
        cudaEventCreateWithFlags(&evFork2, cudaEventDisableTiming);
        cudaEventCreateWithFlags(&evJoin1, cudaEventDisableTiming);
        cudaEventCreateWithFlags(&evJoin2, cudaEventDisableTiming);
        attr_done = true;
    }

    const dim3 blk(256);
    const int mt = cdiv(NTOK_, 128);   // 57
    const int lgrid = NTOK_ / 8;       // 900 blocks, warp per token

    // ---- fork: value projection (depends only on `memory`) runs on s1 ----
    cudaEventRecord(evFork, 0);
    cudaStreamWaitEvent(s1, evFork, 0);
    tgemm<0,2,false,2><<<dim3(4, cdiv(MTOK_,128)), 256, SMT2, s1>>>(
        memory, nullptr, val_w, val_b, (float*)valbf_, nullptr, MTOK_, 256, 256, S_);
    cudaEventRecord(evJoin1, s1);

    // ---- self-attention (main stream) ----
    tgemm<1,3,false,3><<<dim3(8, mt), 256, SMT3>>>(tgt, pos, sa_in_w, sa_in_b,
                                                   q_, (float*)kh_, NTOK_, 512, 256, NQ_);
    tgemm<0,1,false,3><<<dim3(4, mt), 256, SMT3>>>(tgt, nullptr, sa_in_w + 512*256, sa_in_b + 512,
                                                   v_, v_, NTOK_, 256, 256, NQ_);
    prep_v<<<dim3(NQP_ / 32, 64), 256>>>(v_, vh_, vl_);
    attn_mma<<<dim3(cdiv(NQ_, 64), B_ * H_), 128>>>(q_, kh_, kl_, vh_, vl_, attn_);
    tgemm<0,0,false,3><<<dim3(4, mt), 256, SMT3>>>(attn_, nullptr, sa_out_w, sa_out_b,
                                                   sap_, sap_, NTOK_, 256, 256, 0);
    ln_kernel<<<lgrid, blk>>>(tgt, sap_, ln2_g, ln2_b, tgt1_);

    // ---- fork: aw projection on s2 ----
    cudaEventRecord(evFork2, 0);
    cudaStreamWaitEvent(s2, evFork2, 0);
    tgemm<1,0,false,3><<<dim3(3, mt), 256, SMT3, s2>>>(tgt1_, pos, aw_w, aw_b,
                                                       aw_, aw_, NTOK_, 160, 256, 0);
    cudaEventRecord(evJoin2, s2);

    // ---- off projection (main stream) ----
    tgemm<1,0,false,3><<<dim3(5, mt), 256, SMT3>>>(tgt1_, pos, off_w, off_b,
                                                   off_, off_, NTOK_, 320, 256, 0);

    // ---- join: sample needs valbf (s1), aw (s2), off (main) ----
    cudaStreamWaitEvent(0, evJoin1, 0);
    cudaStreamWaitEvent(0, evJoin2, 0);
    sample_kernel<<<NTOK_ * H_ / 8, blk>>>(off_, aw_, refp, valbf_, ca_);
    tgemm<0,0,false,3><<<dim3(4, mt), 256, SMT3>>>(ca_, nullptr, co_w, co_b,
                                                   cap_, cap_, NTOK_, 256, 256, 0);
    ln_kernel<<<lgrid, blk>>>(tgt1_, cap_, ln1_g, ln1_b, tgt2_);

    // ---- FFN (2-term) ----
    tgemm<0,0,true ,2><<<dim3(16, mt), 256, SMT2>>>(tgt2_, nullptr, w1, b1, ffh_, ffh_, NTOK_, 1024, 256, 0);
    tgemm<0,0,false,2><<<dim3(4, mt), 256, SMT2>>>(ffh_, nullptr, w2, b2, ff_, ff_, NTOK_, 256, 1024, 0);
    ln_kernel<<<lgrid, blk>>>(tgt2_, ff_, ln3_g, ln3_b, out);
}

// round 17
// speedup vs baseline: 1.0074x; 1.0074x over previous
#include <cuda_runtime.h>
#include <cuda_bf16.h>
#include <cstdint>

// ---------------- problem constants ----------------
#define NQ_   900
#define NQP_  960
#define B_    8
#define D_    256
#define H_    8
#define DH_   32
#define L_    4
#define P_    5
#define S_    21760
#define DFF_  1024
#define NTOK_ (NQ_ * B_)      // 7200
#define MTOK_ (S_ * B_)       // 174080
#define KOFF_ (B_*H_*NQP_*DH_)   // offset of kl within g_khl

__device__ __constant__ int c_Hl[4]    = {128, 64, 32, 16};
__device__ __constant__ int c_start[4] = {0, 16384, 20480, 21504};

// ---------------- scratch ----------------
__device__ float g_q[B_*H_*NQ_*DH_];
__device__ float g_v[B_*H_*NQ_*DH_];
__device__ __align__(16) __nv_bfloat16 g_khl[2*KOFF_];
__device__ __align__(16) __nv_bfloat16 g_vh[B_*H_*DH_*NQP_];
__device__ __align__(16) __nv_bfloat16 g_vl[B_*H_*DH_*NQP_];
__device__ __align__(16) __nv_bfloat16 g_valbf[B_*H_*S_*DH_];
__device__ __align__(16) __nv_bfloat16 g_ffhbf[NTOK_*DFF_];
__device__ float g_attn[NTOK_*D_];
__device__ float g_saproj[NTOK_*D_];
__device__ float g_tgt1[NTOK_*D_];
__device__ float g_off[NTOK_*(H_*L_*P_*2)];
__device__ float g_aw[NTOK_*(H_*L_*P_)];
__device__ float g_ca[NTOK_*D_];
__device__ float g_caproj[NTOK_*D_];
__device__ float g_tgt2[NTOK_*D_];
__device__ float g_ff[NTOK_*D_];

// ---------------- small helpers ----------------
__device__ __forceinline__ uint32_t su32(const void* p) {
    uint32_t a;
    asm("{ .reg .u64 t; cvta.to.shared.u64 t, %1; cvt.u32.u64 %0, t; }" : "=r"(a) : "l"(p));
    return a;
}
__device__ __forceinline__ uint32_t pk(float a, float b) {
    __nv_bfloat162 h = __floats2bfloat162_rn(a, b);
    return reinterpret_cast<uint32_t&>(h);
}
__device__ __forceinline__ void ldsm4(uint32_t addr, uint32_t* r) {
    asm volatile("ldmatrix.sync.aligned.m8n8.x4.shared.b16 {%0,%1,%2,%3}, [%4];"
                 : "=r"(r[0]), "=r"(r[1]), "=r"(r[2]), "=r"(r[3]) : "r"(addr));
}
#define MMA16816(c, a, b0r, b1r) \
    asm volatile("mma.sync.aligned.m16n8k16.row.col.f32.bf16.bf16.f32 " \
                 "{%0,%1,%2,%3},{%4,%5,%6,%7},{%8,%9},{%0,%1,%2,%3};" \
                 : "+f"((c)[0]), "+f"((c)[1]), "+f"((c)[2]), "+f"((c)[3]) \
                 : "r"((a)[0]), "r"((a)[1]), "r"((a)[2]), "r"((a)[3]), \
                   "r"(b0r), "r"(b1r))

// ================= mma.sync bf16 fp32-emulated GEMM =================
// TERMS==3: D = Ahi*Bhi + Ahi*Blo + Alo*Bhi ; TERMS==2: drops Alo*Bhi.
// ABF16==1: A is already bf16 (= Ahi exactly); straight copy, TERMS must be 2.
#define A_PITCH 80
#define A_TILE  10240
#define B_TILE  5120
#define SMT3 (4*A_TILE + 4*B_TILE)   // 61440
#define SMT2 (2*A_TILE + 4*B_TILE)   // 40960

// OMODE 0: C[r*N+n] fp32
// OMODE 1: heads layout fp32; head hh=n>>5: hh<8 -> C, hh>=8 -> C2 (h'=hh-8)
// OMODE 2: heads layout bf16 into (bf16*)C (N<=256)
// OMODE 3: QK fused: hh<8 -> C fp32 heads (nrows); hh>=8 -> bf16 hi/lo into
//          (bf16*)C2 (+KOFF_ for lo), padded heads layout nrows=NQP_
// OMODE 4: C[r*N+n] bf16 into (bf16*)C
template<int AMODE, int OMODE, bool RELU, int TERMS, int ABF16 = 0>
__global__ void __launch_bounds__(256) tgemm(
    const float* __restrict__ A0, const float* __restrict__ A1,
    const float* __restrict__ W,  const float* __restrict__ bias,
    float* __restrict__ C, float* __restrict__ C2,
    int M, int N, int K, int nrows)
{
    extern __shared__ char sm[];
    constexpr int ATILES = (TERMS == 3) ? 2 : 1;            // hi (+lo)
    constexpr int BBASE  = 2 * ATILES * A_TILE;             // B region start

    const int tid  = threadIdx.x;
    const int lane = tid & 31;
    const int wid  = tid >> 5;
    const int wm   = wid & 3;
    const int wn   = wid >> 2;
    const int colBase = blockIdx.x * 64;
    const int rowBase = blockIdx.y * 128;

    const uint32_t smBase = su32(sm);
    auto AOFFc = [&](int bf, int s) { return (bf * ATILES + s) * A_TILE; };
    auto BOFFc = [&](int bf, int s) { return BBASE + (bf * 2 + s) * B_TILE; };

    float4 pa[4];
    uint4  pab[2];
    float4 pb[2];

    auto ldg_chunk = [&](int k0) {
        if (ABF16) {
            const __nv_bfloat16* Ab = (const __nv_bfloat16*)A0;
#pragma unroll
            for (int i = 0; i < 2; i++) {
                int idx = tid + i * 256;
                int row = idx >> 2, seg = idx & 3;     // 32 bf16/row = 4 x 16B
                int gr = rowBase + row;
                pab[i] = (gr < M) ? *(const uint4*)(Ab + (size_t)gr * K + k0 + seg * 8)
                                  : make_uint4(0, 0, 0, 0);
            }
        } else {
#pragma unroll
            for (int i = 0; i < 4; i++) {
                int idx = tid + i * 256;
                int row = idx >> 3, f4 = idx & 7;
                int gr = rowBase + row;
                float4 v = make_float4(0.f, 0.f, 0.f, 0.f);
                if (gr < M) {
                    v = *(const float4*)(A0 + (size_t)gr * K + k0 + f4 * 4);
                    if (AMODE) {
                        float4 u = *(const float4*)(A1 + (size_t)gr * K + k0 + f4 * 4);
                        v.x += u.x; v.y += u.y; v.z += u.z; v.w += u.w;
                    }
                }
                pa[i] = v;
            }
        }
#pragma unroll
        for (int i = 0; i < 2; i++) {
            int idx = tid + i * 256;
            int row = idx >> 3, f4 = idx & 7;
            int gn = colBase + row;
            pb[i] = (gn < N) ? *(const float4*)(W + (size_t)gn * K + k0 + f4 * 4)
                             : make_float4(0.f, 0.f, 0.f, 0.f);
        }
    };

    auto sts_chunk = [&](int bf) {
        if (ABF16) {
#pragma unroll
            for (int i = 0; i < 2; i++) {
                int idx = tid + i * 256;
                int row = idx >> 2, seg = idx & 3;
                *(uint4*)(sm + AOFFc(bf, 0) + row * A_PITCH + seg * 16) = pab[i];
            }
        } else {
#pragma unroll
            for (int i = 0; i < 4; i++) {
                int idx = tid + i * 256;
                int row = idx >> 3, f4 = idx & 7;
                float4 v = pa[i];
                float hx = __bfloat162float(__float2bfloat16_rn(v.x));
                float hy = __bfloat162float(__float2bfloat16_rn(v.y));
                float hz = __bfloat162float(__float2bfloat16_rn(v.z));
                float hw = __bfloat162float(__float2bfloat16_rn(v.w));
                uint2 Hi = make_uint2(pk(hx, hy), pk(hz, hw));
                *(uint2*)(sm + AOFFc(bf, 0) + row * A_PITCH + f4 * 8) = Hi;
                if (TERMS == 3) {
                    uint2 Lo = make_uint2(pk(v.x - hx, v.y - hy), pk(v.z - hz, v.w - hw));
                    *(uint2*)(sm + AOFFc(bf, 1) + row * A_PITCH + f4 * 8) = Lo;
                }
            }
        }
#pragma unroll
        for (int i = 0; i < 2; i++) {
            int idx = tid + i * 256;
            int row = idx >> 3, f4 = idx & 7;
            float4 v = pb[i];
            float hx = __bfloat162float(__float2bfloat16_rn(v.x));
            float hy = __bfloat162float(__float2bfloat16_rn(v.y));
            float hz = __bfloat162float(__float2bfloat16_rn(v.z));
            float hw = __bfloat162float(__float2bfloat16_rn(v.w));
            uint2 Hi = make_uint2(pk(hx, hy), pk(hz, hw));
            uint2 Lo = make_uint2(pk(v.x - hx, v.y - hy), pk(v.z - hz, v.w - hw));
            *(uint2*)(sm + BOFFc(bf, 0) + row * A_PITCH + f4 * 8) = Hi;
            *(uint2*)(sm + BOFFc(bf, 1) + row * A_PITCH + f4 * 8) = Lo;
        }
    };

    float acc[2][4][4];
#pragma unroll
    for (int tm = 0; tm < 2; tm++)
#pragma unroll
        for (int tn = 0; tn < 4; tn++)
#pragma unroll
            for (int j = 0; j < 4; j++) acc[tm][tn][j] = 0.f;

    const int laneRow  = lane & 15;
    const int laneHalf = (lane & 16) ? 16 : 0;
    const uint32_t aRowOff  = (uint32_t)(wm * 32 + laneRow) * A_PITCH + laneHalf;
    const uint32_t bRowOff0 = (uint32_t)(wn * 32 + laneRow) * A_PITCH + laneHalf;
    const uint32_t bRowOff1 = (uint32_t)(wn * 32 + 16 + laneRow) * A_PITCH + laneHalf;

    const int NC = K >> 5;
    ldg_chunk(0);

    for (int c = 0; c < NC; c++) {
        int bf = c & 1;
        sts_chunk(bf);
        __syncthreads();
        if (c + 1 < NC) ldg_chunk((c + 1) * 32);

        const uint32_t aHiB = smBase + AOFFc(bf, 0) + aRowOff;
        const uint32_t aLoB = smBase + AOFFc(bf, TERMS == 3 ? 1 : 0) + aRowOff;
        const uint32_t bHiB0 = smBase + BOFFc(bf, 0) + bRowOff0;
        const uint32_t bHiB1 = smBase + BOFFc(bf, 0) + bRowOff1;
        const uint32_t bLoB0 = smBase + BOFFc(bf, 1) + bRowOff0;
        const uint32_t bLoB1 = smBase + BOFFc(bf, 1) + bRowOff1;

#pragma unroll
        for (int ks = 0; ks < 2; ks++) {
            uint32_t kof = ks * 32;
            uint32_t aH[2][4], aL[2][4], bH0[4], bH1[4], bL0[4], bL1[4];
            ldsm4(aHiB + kof,                aH[0]);
            ldsm4(aHiB + 16 * A_PITCH + kof, aH[1]);
            if (TERMS == 3) {
                ldsm4(aLoB + kof,                aL[0]);
                ldsm4(aLoB + 16 * A_PITCH + kof, aL[1]);
            }
            ldsm4(bHiB0 + kof, bH0);
            ldsm4(bHiB1 + kof, bH1);
            ldsm4(bLoB0 + kof, bL0);
            ldsm4(bLoB1 + kof, bL1);

            uint32_t b0h[4] = {bH0[0], bH0[1], bH1[0], bH1[1]};
            uint32_t b1h[4] = {bH0[2], bH0[3], bH1[2], bH1[3]};
            uint32_t b0l[4] = {bL0[0], bL0[1], bL1[0], bL1[1]};
            uint32_t b1l[4] = {bL0[2], bL0[3], bL1[2], bL1[3]};

#pragma unroll
            for (int tm = 0; tm < 2; tm++) {
#pragma unroll
                for (int tn = 0; tn < 4; tn++) {
                    MMA16816(acc[tm][tn], aH[tm], b0h[tn], b1h[tn]);
                    MMA16816(acc[tm][tn], aH[tm], b0l[tn], b1l[tn]);
                    if (TERMS == 3)
                        MMA16816(acc[tm][tn], aL[tm], b0h[tn], b1h[tn]);
                }
            }
        }
        // no trailing sync: double buffering makes the pre-MMA sync sufficient
    }

    const int g  = lane >> 2;
    const int t4 = lane & 3;
#pragma unroll
    for (int tm = 0; tm < 2; tm++) {
        int row0 = rowBase + wm * 32 + tm * 16 + g;
#pragma unroll
        for (int tn = 0; tn < 4; tn++) {
            int col = colBase + wn * 32 + tn * 8 + t4 * 2;
            if (col >= N) continue;
            float b0 = bias[col], b1 = bias[col + 1];
            float* cc = acc[tm][tn];
            float v00 = cc[0] + b0, v01 = cc[1] + b1;
            float v10 = cc[2] + b0, v11 = cc[3] + b1;
            if (RELU) {
                v00 = fmaxf(v00, 0.f); v01 = fmaxf(v01, 0.f);
                v10 = fmaxf(v10, 0.f); v11 = fmaxf(v11, 0.f);
            }
            if (OMODE == 0) {
                if (row0 < M)     *(float2*)(C + (size_t)row0 * N + col)       = make_float2(v00, v01);
                if (row0 + 8 < M) *(float2*)(C + (size_t)(row0 + 8) * N + col) = make_float2(v10, v11);
            } else if (OMODE == 1) {
                int hh = col >> 5, wi = col & 31;
                float* dst = (hh < 8) ? C : C2;
                int hp = hh & 7;
                if (row0 < M) {
                    int s = row0 >> 3, bb = row0 & 7;
                    *(float2*)(dst + (((size_t)(bb * 8 + hp)) * nrows + s) * 32 + wi) = make_float2(v00, v01);
                }
                if (row0 + 8 < M) {
                    int r1 = row0 + 8;
                    int s = r1 >> 3, bb = r1 & 7;
                    *(float2*)(dst + (((size_t)(bb * 8 + hp)) * nrows + s) * 32 + wi) = make_float2(v10, v11);
                }
            } else if (OMODE == 2) {
                int hh = col >> 5, wi = col & 31;
                __nv_bfloat16* dst = (__nv_bfloat16*)C;
                if (row0 < M) {
                    int s = row0 >> 3, bb = row0 & 7;
                    *(uint32_t*)(dst + (((size_t)(bb * 8 + hh)) * nrows + s) * 32 + wi) = pk(v00, v01);
                }
                if (row0 + 8 < M) {
                    int r1 = row0 + 8;
                    int s = r1 >> 3, bb = r1 & 7;
                    *(uint32_t*)(dst + (((size_t)(bb * 8 + hh)) * nrows + s) * 32 + wi) = pk(v10, v11);
                }
            } else if (OMODE == 3) {
                int hh = col >> 5, wi = col & 31;
                if (hh < 8) {
                    if (row0 < M) {
                        int s = row0 >> 3, bb = row0 & 7;
                        *(float2*)(C + (((size_t)(bb * 8 + hh)) * nrows + s) * 32 + wi) = make_float2(v00, v01);
                    }
                    if (row0 + 8 < M) {
                        int r1 = row0 + 8;
                        int s = r1 >> 3, bb = r1 & 7;
                        *(float2*)(C + (((size_t)(bb * 8 + hh)) * nrows + s) * 32 + wi) = make_float2(v10, v11);
                    }
                } else {
                    int hp = hh - 8;
                    __nv_bfloat16* kh = (__nv_bfloat16*)C2;
                    if (row0 < M) {
                        int s = row0 >> 3, bb = row0 & 7;
                        size_t o = (((size_t)(bb * 8 + hp)) * NQP_ + s) * 32 + wi;
                        float h0 = __bfloat162float(__float2bfloat16_rn(v00));
                        float h1 = __bfloat162float(__float2bfloat16_rn(v01));
                        *(uint32_t*)(kh + o)         = pk(h0, h1);
                        *(uint32_t*)(kh + KOFF_ + o) = pk(v00 - h0, v01 - h1);
                    }
                    if (row0 + 8 < M) {
                        int r1 = row0 + 8;
                        int s = r1 >> 3, bb = r1 & 7;
                        size_t o = (((size_t)(bb * 8 + hp)) * NQP_ + s) * 32 + wi;
                        float h0 = __bfloat162float(__float2bfloat16_rn(v10));
                        float h1 = __bfloat162float(__float2bfloat16_rn(v11));
                        *(uint32_t*)(kh + o)         = pk(h0, h1);
                        *(uint32_t*)(kh + KOFF_ + o) = pk(v10 - h0, v11 - h1);
                    }
                }
            } else {   // OMODE 4: plain bf16 output
                __nv_bfloat16* dst = (__nv_bfloat16*)C;
                if (row0 < M)     *(uint32_t*)(dst + (size_t)row0 * N + col)       = pk(v00, v01);
                if (row0 + 8 < M) *(uint32_t*)(dst + (size_t)(row0 + 8) * N + col) = pk(v10, v11);
            }
        }
    }
}

// ---------------- prep: V fp32 -> transposed bf16 hi/lo via smem tiles --------
__global__ void prep_v(const float* __restrict__ v,
                       __nv_bfloat16* __restrict__ vh, __nv_bfloat16* __restrict__ vl)
{
    __shared__ float t[32][33];
    const int bh = blockIdx.y;
    const int kt = blockIdx.x * 32;
    const int ch = threadIdx.x & 31;
    const int r  = threadIdx.x >> 5;

#pragma unroll
    for (int i = 0; i < 4; i++) {
        int key = kt + r + i * 8;
        t[r + i * 8][ch] = (key < NQ_) ? v[((size_t)bh * NQ_ + key) * 32 + ch] : 0.f;
    }
    __syncthreads();
#pragma unroll
    for (int i = 0; i < 4; i++) {
        int ch2 = r + i * 8;
        float val = t[ch][ch2];
        __nv_bfloat16 h = __float2bfloat16_rn(val);
        size_t o = ((size_t)bh * 32 + ch2) * NQP_ + kt + ch;
        vh[o] = h;
        vl[o] = __float2bfloat16_rn(val - __bfloat162float(h));
    }
}

// ---------------- mma.sync flash self-attention -------------------------------
#define KS_PITCH 80
#define VS_PITCH 144
__global__ void __launch_bounds__(128) attn_mma(
    const float* __restrict__ q,
    const __nv_bfloat16* __restrict__ kh, const __nv_bfloat16* __restrict__ kl,
    const __nv_bfloat16* __restrict__ vh, const __nv_bfloat16* __restrict__ vl,
    float* __restrict__ out)
{
    __shared__ __align__(16) char KsH[64 * KS_PITCH];
    __shared__ __align__(16) char KsL[64 * KS_PITCH];
    __shared__ __align__(16) char VsH[32 * VS_PITCH];
    __shared__ __align__(16) char VsL[32 * VS_PITCH];

    const int bh   = blockIdx.y;
    const int q0   = blockIdx.x * 64;
    const int tid  = threadIdx.x;
    const int lane = tid & 31;
    const int w    = tid >> 5;
    const int g    = lane >> 2;
    const int t4   = lane & 3;
    const int laneRow  = lane & 15;
    const int laneHalf = (lane & 16) ? 16 : 0;

    const uint32_t sKH = su32(KsH), sKL = su32(KsL);
    const uint32_t sVH = su32(VsH), sVL = su32(VsL);
    const float scale = 0.17677669529663687f;

#pragma unroll
    for (int i = 0; i < 8; i++) {
        int p = tid + i * 128;
        int row = p >> 4, chp = p & 15;
        int gq = q0 + row;
        float a0 = 0.f, a1 = 0.f;
        if (gq < NQ_) {
            const float* src = q + ((size_t)bh * NQ_ + gq) * 32 + chp * 2;
            a0 = src[0] * scale; a1 = src[1] * scale;
        }
        float h0 = __bfloat162float(__float2bfloat16_rn(a0));
        float h1 = __bfloat162float(__float2bfloat16_rn(a1));
        *(uint32_t*)(KsH + row * KS_PITCH + chp * 4) = pk(h0, h1);
        *(uint32_t*)(KsL + row * KS_PITCH + chp * 4) = pk(a0 - h0, a1 - h1);
    }
    __syncthreads();

    uint32_t aQh[2][4], aQl[2][4];
#pragma unroll
    for (int kc = 0; kc < 2; kc++) {
        ldsm4(sKH + (w * 16 + laneRow) * KS_PITCH + laneHalf + kc * 32, aQh[kc]);
        ldsm4(sKL + (w * 16 + laneRow) * KS_PITCH + laneHalf + kc * 32, aQl[kc]);
    }
    __syncthreads();

    float sO[4][4];
#pragma unroll
    for (int tn = 0; tn < 4; tn++)
#pragma unroll
        for (int j = 0; j < 4; j++) sO[tn][j] = 0.f;
    float m0 = -1e30f, m1 = -1e30f, l0 = 0.f, l1 = 0.f;

    for (int kt = 0; kt < NQP_; kt += 64) {
#pragma unroll
        for (int i = 0; i < 2; i++) {
            int idx = tid + i * 128;
            int row = idx >> 2, seg = idx & 3;
            const uint4* srcH = (const uint4*)(kh + ((size_t)bh * NQP_ + kt + row) * 32 + seg * 8);
            const uint4* srcL = (const uint4*)(kl + ((size_t)bh * NQP_ + kt + row) * 32 + seg * 8);
            *(uint4*)(KsH + row * KS_PITCH + seg * 16) = *srcH;
            *(uint4*)(KsL + row * KS_PITCH + seg * 16) = *srcL;
            int vrow = idx >> 3, vseg = idx & 7;
            const uint4* vsrcH = (const uint4*)(vh + ((size_t)bh * 32 + vrow) * NQP_ + kt + vseg * 8);
            const uint4* vsrcL = (const uint4*)(vl + ((size_t)bh * 32 + vrow) * NQP_ + kt + vseg * 8);
            *(uint4*)(VsH + vrow * VS_PITCH + vseg * 16) = *vsrcH;
            *(uint4*)(VsL + vrow * VS_PITCH + vseg * 16) = *vsrcL;
        }
        __syncthreads();

        float sS[8][4];
#pragma unroll
        for (int tn = 0; tn < 8; tn++)
#pragma unroll
            for (int j = 0; j < 4; j++) sS[tn][j] = 0.f;

#pragma unroll
        for (int kc = 0; kc < 2; kc++) {
#pragma unroll
            for (int kg = 0; kg < 4; kg++) {
                uint32_t bKh[4], bKl[4];
                ldsm4(sKH + (kg * 16 + laneRow) * KS_PITCH + laneHalf + kc * 32, bKh);
                ldsm4(sKL + (kg * 16 + laneRow) * KS_PITCH + laneHalf + kc * 32, bKl);
                float* c0 = sS[kg * 2];
                float* c1 = sS[kg * 2 + 1];
                MMA16816(c0, aQh[kc], bKh[0], bKh[2]);
                MMA16816(c0, aQh[kc], bKl[0], bKl[2]);
                MMA16816(c0, aQl[kc], bKh[0], bKh[2]);
                MMA16816(c1, aQh[kc], bKh[1], bKh[3]);
                MMA16816(c1, aQh[kc], bKl[1], bKl[3]);
                MMA16816(c1, aQl[kc], bKh[1], bKh[3]);
            }
        }

        if (kt + 64 > NQ_) {
#pragma unroll
            for (int tn = 0; tn < 8; tn++) {
                int k0 = kt + tn * 8 + t4 * 2;
                if (k0 >= NQ_)     { sS[tn][0] = -1e30f; sS[tn][2] = -1e30f; }
                if (k0 + 1 >= NQ_) { sS[tn][1] = -1e30f; sS[tn][3] = -1e30f; }
            }
        }

        float mx0 = -1e30f, mx1 = -1e30f;
#pragma unroll
        for (int tn = 0; tn < 8; tn++) {
            mx0 = fmaxf(mx0, fmaxf(sS[tn][0], sS[tn][1]));
            mx1 = fmaxf(mx1, fmaxf(sS[tn][2], sS[tn][3]));
        }
        mx0 = fmaxf(mx0, __shfl_xor_sync(0xffffffffu, mx0, 1));
        mx0 = fmaxf(mx0, __shfl_xor_sync(0xffffffffu, mx0, 2));
        mx1 = fmaxf(mx1, __shfl_xor_sync(0xffffffffu, mx1, 1));
        mx1 = fmaxf(mx1, __shfl_xor_sync(0xffffffffu, mx1, 2));
        float nm0 = fmaxf(m0, mx0), nm1 = fmaxf(m1, mx1);
        float cr0 = __expf(m0 - nm0), cr1 = __expf(m1 - nm1);
        m0 = nm0; m1 = nm1;
        float rs0 = 0.f, rs1 = 0.f;
#pragma unroll
        for (int tn = 0; tn < 8; tn++) {
            sS[tn][0] = __expf(sS[tn][0] - nm0);
            sS[tn][1] = __expf(sS[tn][1] - nm0);
            sS[tn][2] = __expf(sS[tn][2] - nm1);
            sS[tn][3] = __expf(sS[tn][3] - nm1);
            rs0 += sS[tn][0] + sS[tn][1];
            rs1 += sS[tn][2] + sS[tn][3];
        }
        rs0 += __shfl_xor_sync(0xffffffffu, rs0, 1);
        rs0 += __shfl_xor_sync(0xffffffffu, rs0, 2);
        rs1 += __shfl_xor_sync(0xffffffffu, rs1, 1);
        rs1 += __shfl_xor_sync(0xffffffffu, rs1, 2);
        l0 = l0 * cr0 + rs0;
        l1 = l1 * cr1 + rs1;
#pragma unroll
        for (int tn = 0; tn < 4; tn++) {
            sO[tn][0] *= cr0; sO[tn][1] *= cr0;
            sO[tn][2] *= cr1; sO[tn][3] *= cr1;
        }

#pragma unroll
        for (int kc = 0; kc < 4; kc++) {
            const float* cA = sS[kc * 2];
            const float* cB = sS[kc * 2 + 1];
            float hA0 = __bfloat162float(__float2bfloat16_rn(cA[0]));
            float hA1 = __bfloat162float(__float2bfloat16_rn(cA[1]));
            float hA2 = __bfloat162float(__float2bfloat16_rn(cA[2]));
            float hA3 = __bfloat162float(__float2bfloat16_rn(cA[3]));
            float hB0 = __bfloat162float(__float2bfloat16_rn(cB[0]));
            float hB1 = __bfloat162float(__float2bfloat16_rn(cB[1]));
            float hB2 = __bfloat162float(__float2bfloat16_rn(cB[2]));
            float hB3 = __bfloat162float(__float2bfloat16_rn(cB[3]));
            uint32_t pH[4] = { pk(hA0, hA1), pk(hA2, hA3), pk(hB0, hB1), pk(hB2, hB3) };
            uint32_t pL[4] = { pk(cA[0]-hA0, cA[1]-hA1), pk(cA[2]-hA2, cA[3]-hA3),
                               pk(cB[0]-hB0, cB[1]-hB1), pk(cB[2]-hB2, cB[3]-hB3) };
#pragma unroll
            for (int ng = 0; ng < 2; ng++) {
                uint32_t bVh[4], bVl[4];
                ldsm4(sVH + (ng * 16 + laneRow) * VS_PITCH + laneHalf + kc * 32, bVh);
                ldsm4(sVL + (ng * 16 + laneRow) * VS_PITCH + laneHalf + kc * 32, bVl);
                float* o0 = sO[ng * 2];
                float* o1 = sO[ng * 2 + 1];
                MMA16816(o0, pH, bVh[0], bVh[2]);
                MMA16816(o0, pH, bVl[0], bVl[2]);
                MMA16816(o0, pL, bVh[0], bVh[2]);
                MMA16816(o1, pH, bVh[1], bVh[3]);
                MMA16816(o1, pH, bVl[1], bVl[3]);
                MMA16816(o1, pL, bVh[1], bVh[3]);
            }
        }
        __syncthreads();
    }

    const int b = bh >> 3, h = bh & 7;
    float inv0 = 1.f / l0, inv1 = 1.f / l1;
    int r0 = q0 + w * 16 + g;
    int r1 = r0 + 8;
#pragma unroll
    for (int tn = 0; tn < 4; tn++) {
        int col = h * 32 + tn * 8 + t4 * 2;
        if (r0 < NQ_)
            *(float2*)(out + ((size_t)r0 * B_ + b) * D_ + col) =
                make_float2(sO[tn][0] * inv0, sO[tn][1] * inv0);
        if (r1 < NQ_)
            *(float2*)(out + ((size_t)r1 * B_ + b) * D_ + col) =
                make_float2(sO[tn][2] * inv1, sO[tn][3] * inv1);
    }
}

// ---------------- layer norm: warp per token, single-pass sum+sumsq ----------
__global__ void __launch_bounds__(256) ln_kernel(
    const float* __restrict__ a, const float* __restrict__ r,
    const float* __restrict__ g, const float* __restrict__ be,
    float* __restrict__ out)
{
    const int lane = threadIdx.x & 31;
    const int t = blockIdx.x * 8 + (threadIdx.x >> 5);

    const float* pa = a + (size_t)t * D_;
    const float* pr = r + (size_t)t * D_;

    float x[8];
    float s = 0.f, s2 = 0.f;
#pragma unroll
    for (int j = 0; j < 8; j++) {
        int i = lane + j * 32;
        float v = pa[i] + pr[i];
        x[j] = v;
        s += v;
        s2 = fmaf(v, v, s2);
    }
#pragma unroll
    for (int o = 16; o; o >>= 1) {
        s  += __shfl_xor_sync(0xffffffffu, s,  o);
        s2 += __shfl_xor_sync(0xffffffffu, s2, o);
    }
    float mean = s * (1.f / 256.f);
    float var  = fmaf(s2, 1.f / 256.f, -mean * mean);
    float rstd = rsqrtf(var + 1e-5f);

    float* po = out + (size_t)t * D_;
#pragma unroll
    for (int j = 0; j < 8; j++) {
        int i = lane + j * 32;
        po[i] = (x[j] - mean) * rstd * g[i] + be[i];
    }
}

// ---------------- deformable sampling (bf16 value) ----------------
__global__ void sample_kernel(const float* __restrict__ off, const float* __restrict__ awl,
                              const float* __restrict__ refp,
                              const __nv_bfloat16* __restrict__ val,
                              float* __restrict__ out)
{
    const int gw   = blockIdx.x * 8 + (threadIdx.x >> 5);
    const int lane = threadIdx.x & 31;
    const int t = gw >> 3;
    const int h = gw & 7;
    const int b = t & 7;

    float logit = (lane < 20) ? awl[(size_t)t * 160 + h * 20 + lane] : -1e30f;
    float mx = logit;
#pragma unroll
    for (int o = 16; o; o >>= 1) mx = fmaxf(mx, __shfl_xor_sync(0xffffffffu, mx, o));
    float e = (lane < 20) ? __expf(logit - mx) : 0.f;
    float sm = e;
#pragma unroll
    for (int o = 16; o; o >>= 1) sm += __shfl_xor_sync(0xffffffffu, sm, o);
    float pw = e / sm;

    const float* rp = refp + (size_t)t * 16;
    const float* op = off + (size_t)t * 320 + h * 40;

    float acc = 0.f;
#pragma unroll
    for (int l = 0; l < 4; l++) {
        const int Wl = c_Hl[l];
        const int Hl = c_Hl[l];
        const float r0 = rp[l * 4 + 0], r1 = rp[l * 4 + 1];
        const float r2 = rp[l * 4 + 2], r3 = rp[l * 4 + 3];
        const __nv_bfloat16* vbase = val + ((size_t)(b * 8 + h) * S_ + c_start[l]) * 32;
#pragma unroll
        for (int p = 0; p < 5; p++) {
            float aw = __shfl_sync(0xffffffffu, pw, l * 5 + p);
            float ox = op[(l * 5 + p) * 2 + 0];
            float oy = op[(l * 5 + p) * 2 + 1];
            float x = (r0 + ox * 0.2f * r2 * 0.5f) * (float)Wl - 0.5f;
            float y = (r1 + oy * 0.2f * r3 * 0.5f) * (float)Hl - 0.5f;
            float x0f = floorf(x), y0f = floorf(y);
            float fx = x - x0f, fy = y - y0f;
            int x0 = (int)x0f, y0 = (int)y0f;
#pragma unroll
            for (int dy = 0; dy < 2; dy++) {
#pragma unroll
                for (int dx = 0; dx < 2; dx++) {
                    int xi = x0 + dx, yi = y0 + dy;
                    float w = (dx ? fx : 1.f - fx) * (dy ? fy : 1.f - fy);
                    bool valid = (xi >= 0) && (xi < Wl) && (yi >= 0) && (yi < Hl);
                    if (valid && w != 0.f)
                        acc = fmaf(aw * w,
                                   __bfloat162float(vbase[((size_t)yi * Wl + xi) * 32 + lane]),
                                   acc);
                }
            }
        }
    }
    out[(size_t)t * D_ + h * 32 + lane] = acc;
}

// ---------------- host launcher ----------------
static inline int cdiv(int a, int b) { return (a + b - 1) / b; }

extern "C" void kernel_launch(void* const* d_in, const int* in_sizes, int n_in,
                              void* d_out, int out_size)
{
    const float* tgt     = (const float*)d_in[0];
    const float* pos     = (const float*)d_in[1];
    const float* refp    = (const float*)d_in[2];
    const float* memory  = (const float*)d_in[3];
    const float* sa_in_w = (const float*)d_in[4];
    const float* sa_in_b = (const float*)d_in[5];
    const float* sa_out_w= (const float*)d_in[6];
    const float* sa_out_b= (const float*)d_in[7];
    const float* off_w   = (const float*)d_in[8];
    const float* off_b   = (const float*)d_in[9];
    const float* aw_w    = (const float*)d_in[10];
    const float* aw_b    = (const float*)d_in[11];
    const float* val_w   = (const float*)d_in[12];
    const float* val_b   = (const float*)d_in[13];
    const float* co_w    = (const float*)d_in[14];
    const float* co_b    = (const float*)d_in[15];
    const float* w1      = (const float*)d_in[16];
    const float* b1      = (const float*)d_in[17];
    const float* w2      = (const float*)d_in[18];
    const float* b2      = (const float*)d_in[19];
    const float* ln1_g   = (const float*)d_in[20];
    const float* ln1_b   = (const float*)d_in[21];
    const float* ln2_g   = (const float*)d_in[22];
    const float* ln2_b   = (const float*)d_in[23];
    const float* ln3_g   = (const float*)d_in[24];
    const float* ln3_b   = (const float*)d_in[25];
    float* out = (float*)d_out;

    void *p;
    cudaGetSymbolAddress(&p, g_q);      float* q_     = (float*)p;
    cudaGetSymbolAddress(&p, g_v);      float* v_     = (float*)p;
    cudaGetSymbolAddress(&p, g_khl);    __nv_bfloat16* kh_ = (__nv_bfloat16*)p;
    __nv_bfloat16* kl_ = kh_ + KOFF_;
    cudaGetSymbolAddress(&p, g_vh);     __nv_bfloat16* vh_ = (__nv_bfloat16*)p;
    cudaGetSymbolAddress(&p, g_vl);     __nv_bfloat16* vl_ = (__nv_bfloat16*)p;
    cudaGetSymbolAddress(&p, g_valbf);  __nv_bfloat16* valbf_ = (__nv_bfloat16*)p;
    cudaGetSymbolAddress(&p, g_ffhbf);  __nv_bfloat16* ffhbf_ = (__nv_bfloat16*)p;
    cudaGetSymbolAddress(&p, g_attn);   float* attn_  = (float*)p;
    cudaGetSymbolAddress(&p, g_saproj); float* sap_   = (float*)p;
    cudaGetSymbolAddress(&p, g_tgt1);   float* tgt1_  = (float*)p;
    cudaGetSymbolAddress(&p, g_off);    float* off_   = (float*)p;
    cudaGetSymbolAddress(&p, g_aw);     float* aw_    = (float*)p;
    cudaGetSymbolAddress(&p, g_ca);     float* ca_    = (float*)p;
    cudaGetSymbolAddress(&p, g_caproj); float* cap_   = (float*)p;
    cudaGetSymbolAddress(&p, g_tgt2);   float* tgt2_  = (float*)p;
    cudaGetSymbolAddress(&p, g_ff);     float* ff_    = (float*)p;

    // one-time setup (first call is the uncaptured correctness run)
    static cudaStream_t s1 = nullptr, s2 = nullptr;
    static cudaEvent_t evFork = nullptr, evFork2 = nullptr, evJoin1 = nullptr, evJoin2 = nullptr;
    static bool attr_done = false;
    if (!attr_done) {
        cudaFuncSetAttribute(tgemm<1,3,false,3>,   cudaFuncAttributeMaxDynamicSharedMemorySize, SMT3);
        cudaFuncSetAttribute(tgemm<0,1,false,3>,   cudaFuncAttributeMaxDynamicSharedMemorySize, SMT3);
        cudaFuncSetAttribute(tgemm<0,0,false,3>,   cudaFuncAttributeMaxDynamicSharedMemorySize, SMT3);
        cudaFuncSetAttribute(tgemm<0,2,false,2>,   cudaFuncAttributeMaxDynamicSharedMemorySize, SMT2);
        cudaFuncSetAttribute(tgemm<1,0,false,3>,   cudaFuncAttributeMaxDynamicSharedMemorySize, SMT3);
        cudaFuncSetAttribute(tgemm<0,4,true ,2>,   cudaFuncAttributeMaxDynamicSharedMemorySize, SMT2);
        cudaFuncSetAttribute(tgemm<0,0,false,2,1>, cudaFuncAttributeMaxDynamicSharedMemorySize, SMT2);
        cudaStreamCreateWithFlags(&s1, cudaStreamNonBlocking);
        cudaStreamCreateWithFlags(&s2, cudaStreamNonBlocking);
        cudaEventCreateWithFlags(&evFork,  cudaEventDisableTiming);
        cudaEventCreateWithFlags(&evFork2, cudaEventDisableTiming);
        cudaEventCreateWithFlags(&evJoin1, cudaEventDisableTiming);
        cudaEventCreateWithFlags(&evJoin2, cudaEventDisableTiming);
        attr_done = true;
    }

    const dim3 blk(256);
    const int mt = cdiv(NTOK_, 128);   // 57
    const int lgrid = NTOK_ / 8;       // 900 blocks, warp per token

    // ---- fork: value projection (depends only on `memory`) runs on s1 ----
    cudaEventRecord(evFork, 0);
    cudaStreamWaitEvent(s1, evFork, 0);
    tgemm<0,2,false,2><<<dim3(4, cdiv(MTOK_,128)), 256, SMT2, s1>>>(
        memory, nullptr, val_w, val_b, (float*)valbf_, nullptr, MTOK_, 256, 256, S_);
    cudaEventRecord(evJoin1, s1);

    // ---- self-attention (main stream) ----
    tgemm<1,3,false,3><<<dim3(8, mt), 256, SMT3>>>(tgt, pos, sa_in_w, sa_in_b,
                                                   q_, (float*)kh_, NTOK_, 512, 256, NQ_);
    tgemm<0,1,false,3><<<dim3(4, mt), 256, SMT3>>>(tgt, nullptr, sa_in_w + 512*256, sa_in_b + 512,
                                                   v_, v_, NTOK_, 256, 256, NQ_);
    prep_v<<<dim3(NQP_ / 32, 64), 256>>>(v_, vh_, vl_);
    attn_mma<<<dim3(cdiv(NQ_, 64), B_ * H_), 128>>>(q_, kh_, kl_, vh_, vl_, attn_);
    tgemm<0,0,false,3><<<dim3(4, mt), 256, SMT3>>>(attn_, nullptr, sa_out_w, sa_out_b,
                                                   sap_, sap_, NTOK_, 256, 256, 0);
    ln_kernel<<<lgrid, blk>>>(tgt, sap_, ln2_g, ln2_b, tgt1_);

    // ---- fork: aw projection on s2 ----
    cudaEventRecord(evFork2, 0);
    cudaStreamWaitEvent(s2, evFork2, 0);
    tgemm<1,0,false,3><<<dim3(3, mt), 256, SMT3, s2>>>(tgt1_, pos, aw_w, aw_b,
                                                       aw_, aw_, NTOK_, 160, 256, 0);
    cudaEventRecord(evJoin2, s2);

    // ---- off projection (main stream) ----
    tgemm<1,0,false,3><<<dim3(5, mt), 256, SMT3>>>(tgt1_, pos, off_w, off_b,
                                                   off_, off_, NTOK_, 320, 256, 0);

    // ---- join: sample needs valbf (s1), aw (s2), off (main) ----
    cudaStreamWaitEvent(0, evJoin1, 0);
    cudaStreamWaitEvent(0, evJoin2, 0);
    sample_kernel<<<NTOK_ * H_ / 8, blk>>>(off_, aw_, refp, valbf_, ca_);
    tgemm<0,0,false,3><<<dim3(4, mt), 256, SMT3>>>(ca_, nullptr, co_w, co_b,
                                                   cap_, cap_, NTOK_, 256, 256, 0);
    ln_kernel<<<lgrid, blk>>>(tgt1_, cap_, ln1_g, ln1_b, tgt2_);

    // ---- FFN: hidden tensor kept in bf16 (bit-identical for 2-term FFN2) ----
    tgemm<0,4,true ,2><<<dim3(16, mt), 256, SMT2>>>(tgt2_, nullptr, w1, b1,
                                                    (float*)ffhbf_, nullptr, NTOK_, 1024, 256, 0);
    tgemm<0,0,false,2,1><<<dim3(4, mt), 256, SMT2>>>((const float*)ffhbf_, nullptr, w2, b2,
                                                     ff_, ff_, NTOK_, 256, 1024, 0);
    ln_kernel<<<lgrid, blk>>>(tgt2_, ff_, ln3_g, ln3_b, out);
}